// round 17
// baseline (speedup 1.0000x reference)
#include <cuda_runtime.h>
#include <cuda_fp16.h>
#include <cstdint>
#include <math.h>

// Problem constants
#define BATCH   2
#define TSEQ    2048
#define CDIM    1024
#define HEADS   16
#define HD      64
#define BT      (BATCH * TSEQ)          // 4096 rows
#define QKVDIM  (3 * CDIM)              // 3072

// Scratch (allocation-free rule: __device__ globals) — fp16
__device__ __half g_qkv[(size_t)BT * QKVDIM];    // q(scaled,roped) k(roped) v
__device__ __half g_ao [(size_t)BT * CDIM];      // attention output
__device__ __half g_xr [(size_t)BT * CDIM];      // x, fp16
__device__ __half g_wq [(size_t)QKVDIM * CDIM];  // qkv_w, fp16
__device__ __half g_wp [(size_t)CDIM * CDIM];    // proj_w, fp16

#define QSCALE 0.1803368801111204f   // 0.125 * log2(e)

__device__ __forceinline__ uint32_t smem_u32(const void* p) {
    uint32_t a;
    asm("{ .reg .u64 t; cvta.to.shared.u64 t, %1; cvt.u32.u64 %0, t; }"
        : "=r"(a) : "l"(p));
    return a;
}
__device__ __forceinline__ void cp_async16(uint32_t dst, const void* src) {
    asm volatile("cp.async.cg.shared.global [%0], [%1], 16;"
                 :: "r"(dst), "l"(src));
}
__device__ __forceinline__ void ldsm4(uint32_t& r0, uint32_t& r1,
                                      uint32_t& r2, uint32_t& r3, uint32_t addr) {
    asm volatile("ldmatrix.sync.aligned.m8n8.x4.shared.b16 {%0,%1,%2,%3}, [%4];"
                 : "=r"(r0), "=r"(r1), "=r"(r2), "=r"(r3) : "r"(addr));
}
__device__ __forceinline__ void ldsm4t(uint32_t& r0, uint32_t& r1,
                                       uint32_t& r2, uint32_t& r3, uint32_t addr) {
    asm volatile("ldmatrix.sync.aligned.m8n8.x4.trans.shared.b16 {%0,%1,%2,%3}, [%4];"
                 : "=r"(r0), "=r"(r1), "=r"(r2), "=r"(r3) : "r"(addr));
}
// m16n8k16 fp16 -> fp32 accumulate
__device__ __forceinline__ void mma_f16(
    float& c0, float& c1, float& c2, float& c3,
    uint32_t a0, uint32_t a1, uint32_t a2, uint32_t a3,
    uint32_t b0, uint32_t b1)
{
    asm volatile(
        "mma.sync.aligned.m16n8k16.row.col.f32.f16.f16.f32 "
        "{%0,%1,%2,%3}, {%4,%5,%6,%7}, {%8,%9}, {%0,%1,%2,%3};"
        : "+f"(c0), "+f"(c1), "+f"(c2), "+f"(c3)
        : "r"(a0), "r"(a1), "r"(a2), "r"(a3), "r"(b0), "r"(b1));
}

// ---------------------------------------------------------------------------
// Single fused pre-convert pass: x, qkv_w, proj_w -> fp16
// ---------------------------------------------------------------------------
__global__ __launch_bounds__(256) void to_fp16_all(
    const float4* __restrict__ s0, __half2* __restrict__ d0, int n0,
    const float4* __restrict__ s1, __half2* __restrict__ d1, int n1,
    const float4* __restrict__ s2, __half2* __restrict__ d2, int n2)
{
    const int total = n0 + n1 + n2;
    for (int i = blockIdx.x * blockDim.x + threadIdx.x; i < total;
         i += gridDim.x * blockDim.x) {
        const float4* s; __half2* d; int j;
        if (i < n0)           { s = s0; d = d0; j = i; }
        else if (i < n0 + n1) { s = s1; d = d1; j = i - n0; }
        else                  { s = s2; d = d2; j = i - n0 - n1; }
        float4 v = s[j];
        d[2 * j]     = __floats2half2_rn(v.x, v.y);
        d[2 * j + 1] = __floats2half2_rn(v.z, v.w);
    }
}

// ---------------------------------------------------------------------------
// FP16 mma.sync GEMM, BK=64, 3-stage cp.async pipeline, ldmatrix fragments
// with explicit double-buffering across k16 sub-steps.
// MODE 0: plain fp32-store epilogue (proj GEMM).  MODE 1: fused RoPE, fp16.
// ---------------------------------------------------------------------------
#define TM  128
#define TN  128
#define BKF 64
#define SSTRH 72
#define STGH (TM * SSTRH)
#define NSTAGE 3
#define GEMM_SMEM (NSTAGE * 2 * STGH * 2)   // 110,592 bytes

template <int MODE>
__global__ __launch_bounds__(256, 2) void gemm_f16_nt(
    const __half* __restrict__ A, const __half* __restrict__ B,
    void* __restrict__ Cv, int M, int N, int K,
    const float* __restrict__ cs, const float* __restrict__ sn)
{
    extern __shared__ __align__(16) __half smh[];

    const int tid  = threadIdx.x;
    const int wid  = tid >> 5;
    const int lane = tid & 31;
    const int g = lane >> 2;
    const int t = lane & 3;
    const int rl = lane & 7;
    const int wm = (wid & 3) * 32;
    const int wn = (wid >> 2) * 64;
    const int m0 = blockIdx.y * TM;
    const int n0 = blockIdx.x * TN;

    const int a_row = wm + rl + ((lane & 8) ? 8 : 0);
    const int a_k   = (lane & 16) ? 8 : 0;
    const int b_row = wn + rl + ((lane & 16) ? 8 : 0);
    const int b_k   = (lane & 8) ? 8 : 0;

    float c[2][8][4];
#pragma unroll
    for (int mi = 0; mi < 2; mi++)
#pragma unroll
        for (int ni = 0; ni < 8; ni++)
#pragma unroll
            for (int r = 0; r < 4; r++) c[mi][ni][r] = 0.0f;

    const int nch = K / BKF;

    auto issue_load = [&](int s, int k0) {
        __half* As = smh + s * 2 * STGH;
        __half* Bs = As + STGH;
#pragma unroll
        for (int i = 0; i < 4; i++) {
            int e   = tid + i * 256;
            int row = e >> 3;
            int u   = (e & 7) * 8;
            cp_async16(smem_u32(As + row * SSTRH + u),
                       A + (size_t)(m0 + row) * K + k0 + u);
            cp_async16(smem_u32(Bs + row * SSTRH + u),
                       B + (size_t)(n0 + row) * K + k0 + u);
        }
    };

    issue_load(0, 0);
    asm volatile("cp.async.commit_group;");
    if (nch > 1) issue_load(1, BKF);
    asm volatile("cp.async.commit_group;");

    for (int cch = 0; cch < nch; cch++) {
        asm volatile("cp.async.wait_group 1;");
        __syncthreads();
        if (cch + 2 < nch) issue_load((cch + 2) % NSTAGE, (cch + 2) * BKF);
        asm volatile("cp.async.commit_group;");

        const __half* As = smh + (cch % NSTAGE) * 2 * STGH;
        const __half* Bs = As + STGH;
        const uint32_t a_base = smem_u32(As) + (uint32_t)((a_row * SSTRH + a_k) * 2);
        const uint32_t b_base = smem_u32(Bs) + (uint32_t)((b_row * SSTRH + b_k) * 2);

        // Fragment double-buffers (ping-pong across k16 sub-steps)
        uint32_t af[2][2][4];
        uint32_t bf[2][8][2];

        // preload ks8 = 0 into buffer 0
#pragma unroll
        for (int mi = 0; mi < 2; mi++)
            ldsm4(af[0][mi][0], af[0][mi][1], af[0][mi][2], af[0][mi][3],
                  a_base + (uint32_t)(mi * 16 * SSTRH * 2));
#pragma unroll
        for (int p = 0; p < 4; p++)
            ldsm4(bf[0][2 * p][0], bf[0][2 * p][1],
                  bf[0][2 * p + 1][0], bf[0][2 * p + 1][1],
                  b_base + (uint32_t)(p * 16 * SSTRH * 2));

#pragma unroll
        for (int ks8 = 0; ks8 < 4; ks8++) {
            const int cur = ks8 & 1;
            const int nxt = cur ^ 1;
            if (ks8 < 3) {
                const uint32_t ko = (uint32_t)((ks8 + 1) * 16 * 2);
#pragma unroll
                for (int mi = 0; mi < 2; mi++)
                    ldsm4(af[nxt][mi][0], af[nxt][mi][1],
                          af[nxt][mi][2], af[nxt][mi][3],
                          a_base + (uint32_t)(mi * 16 * SSTRH * 2) + ko);
#pragma unroll
                for (int p = 0; p < 4; p++)
                    ldsm4(bf[nxt][2 * p][0], bf[nxt][2 * p][1],
                          bf[nxt][2 * p + 1][0], bf[nxt][2 * p + 1][1],
                          b_base + (uint32_t)(p * 16 * SSTRH * 2) + ko);
            }
#pragma unroll
            for (int mi = 0; mi < 2; mi++)
#pragma unroll
                for (int ni = 0; ni < 8; ni++)
                    mma_f16(c[mi][ni][0], c[mi][ni][1], c[mi][ni][2], c[mi][ni][3],
                            af[cur][mi][0], af[cur][mi][1],
                            af[cur][mi][2], af[cur][mi][3],
                            bf[cur][ni][0], bf[cur][ni][1]);
        }
    }

#pragma unroll
    for (int mi = 0; mi < 2; mi++) {
        const int row = m0 + wm + mi * 16 + g;
#pragma unroll
        for (int ni = 0; ni < 8; ni++) {
            const int col = n0 + wn + ni * 8 + 2 * t;
            float v0 = c[mi][ni][0], v1 = c[mi][ni][1];
            float v2 = c[mi][ni][2], v3 = c[mi][ni][3];
            if (MODE == 1) {
                if (col < 2 * CDIM) {
                    const int i  = (col & 63) >> 1;
                    const int t0 = row & (TSEQ - 1);
                    const int t1 = (row + 8) & (TSEQ - 1);
                    float c0v = __ldg(cs + t0 * 32 + i);
                    float s0v = __ldg(sn + t0 * 32 + i);
                    float c1v = __ldg(cs + t1 * 32 + i);
                    float s1v = __ldg(sn + t1 * 32 + i);
                    float r0 = v0 * c0v - v1 * s0v;
                    float r1 = v0 * s0v + v1 * c0v;
                    float r2 = v2 * c1v - v3 * s1v;
                    float r3 = v2 * s1v + v3 * c1v;
                    if (col < CDIM) {
                        r0 *= QSCALE; r1 *= QSCALE; r2 *= QSCALE; r3 *= QSCALE;
                    }
                    v0 = r0; v1 = r1; v2 = r2; v3 = r3;
                }
                __half* Ch = (__half*)Cv;
                *(__half2*)(Ch + (size_t)row * N + col) = __floats2half2_rn(v0, v1);
                *(__half2*)(Ch + (size_t)(row + 8) * N + col) = __floats2half2_rn(v2, v3);
            } else {
                float* Cf = (float*)Cv;
                *(float2*)(Cf + (size_t)row * N + col) = make_float2(v0, v1);
                *(float2*)(Cf + (size_t)(row + 8) * N + col) = make_float2(v2, v3);
            }
        }
    }
}

// ---------------------------------------------------------------------------
// Flash attention, fp16 m16n8k16, 3-stage cp.async K/V pipeline, ldmatrix
// (+trans for V), packed-half exp2 softmax, skip-rescale when alpha==1.
// ---------------------------------------------------------------------------
#define AM 128
#define AN 64
#define PBSTR 72
#define KVSTGH (AN * 64)               // halves per K or V stage (8KB)
#define KVNST 3
#define ATTN_SMEM ((2 * KVNST * KVSTGH + AM * PBSTR) * 2)   // 67,584 bytes

__global__ __launch_bounds__(256, 2) void attn_mma(
    const __half* __restrict__ qkv, __half* __restrict__ ao)
{
    extern __shared__ __align__(16) __half smA[];
    __half* Pb = smA + 2 * KVNST * KVSTGH;   // [128][72]: Q staging, then P

    const int m0 = (gridDim.x - 1 - blockIdx.x) * AM;   // long-first
    const int h  = blockIdx.y;
    const int b  = blockIdx.z;
    const int tid = threadIdx.x;
    const int wid = tid >> 5, lane = tid & 31;
    const int g = lane >> 2, t = lane & 3;
    const int rl = lane & 7;
    const int wrow = wid * 16;

    const __half* kvb = qkv + (size_t)b * TSEQ * QKVDIM + CDIM + h * HD;

    auto issue_kv = [&](int s, int n0) {
        __half* Ks = smA + s * 2 * KVSTGH;
        __half* Vs = Ks + KVSTGH;
        const __half* kb = kvb + (size_t)n0 * QKVDIM;
        const __half* vb = kb + CDIM;
#pragma unroll
        for (int i = 0; i < 2; i++) {
            int e   = tid + i * 256;
            int row = e >> 3;
            int u   = e & 7;
            int u2  = u ^ (row & 7);
            cp_async16(smem_u32(Ks + row * 64 + u2 * 8),
                       kb + (size_t)row * QKVDIM + u * 8);
            cp_async16(smem_u32(Vs + row * 64 + u2 * 8),
                       vb + (size_t)row * QKVDIM + u * 8);
        }
    };

    const int ntiles = (m0 + AM) / AN;   // >= 2 always

    // ---- Prologue: Q stage (group 0), then KV tiles 0 and 1 ----
    {
        const __half* qbase = qkv + ((size_t)(b * TSEQ + m0)) * QKVDIM + h * HD;
#pragma unroll
        for (int i = 0; i < 4; i++) {
            int e   = tid + i * 256;
            int row = e >> 3;
            int u   = e & 7;
            cp_async16(smem_u32(Pb + row * PBSTR + u * 8),
                       qbase + (size_t)row * QKVDIM + u * 8);
        }
    }
    asm volatile("cp.async.commit_group;");
    issue_kv(0, 0);
    asm volatile("cp.async.commit_group;");
    issue_kv(1, AN);
    asm volatile("cp.async.commit_group;");

    // Wait for Q (allow both KV tiles outstanding)
    asm volatile("cp.async.wait_group 2;");
    __syncthreads();

    const uint32_t pb_u32 = smem_u32(Pb);
    const uint32_t qrow_off =
        (uint32_t)(((wrow + rl + ((lane & 8) ? 8 : 0)) * PBSTR
                    + ((lane & 16) ? 8 : 0)) * 2);
    uint32_t qa[4][4];
#pragma unroll
    for (int ks8 = 0; ks8 < 4; ks8++)
        ldsm4(qa[ks8][0], qa[ks8][1], qa[ks8][2], qa[ks8][3],
              pb_u32 + qrow_off + (uint32_t)(ks8 * 16 * 2));

    float o[8][4];
#pragma unroll
    for (int nj = 0; nj < 8; nj++)
#pragma unroll
        for (int r = 0; r < 4; r++) o[nj][r] = 0.0f;
    float mx0 = -1e30f, mx1 = -1e30f, l0 = 0.0f, l1 = 0.0f;

    for (int kt = 0; kt < ntiles; kt++) {
        const int n0 = kt * AN;
        asm volatile("cp.async.wait_group 1;");   // tile kt ready, kt+1 in flight
        __syncthreads();                          // prior iter's reads done CTA-wide
        if (kt + 2 < ntiles) {
            issue_kv((kt + 2) % KVNST, n0 + 2 * AN);
            asm volatile("cp.async.commit_group;");
        } else {
            asm volatile("cp.async.commit_group;");   // keep group count moving
        }
        const __half* Ks = smA + (kt % KVNST) * 2 * KVSTGH;
        const __half* Vs = Ks + KVSTGH;
        const uint32_t ks_u32 = smem_u32(Ks);
        const uint32_t vs_u32 = smem_u32(Vs);

        // ---- S = Q K^T ----
        float s[8][4];
#pragma unroll
        for (int nj = 0; nj < 8; nj++)
#pragma unroll
            for (int r = 0; r < 4; r++) s[nj][r] = 0.0f;
#pragma unroll
        for (int ks8 = 0; ks8 < 4; ks8++) {
#pragma unroll
            for (int p = 0; p < 4; p++) {
                int krow = p * 16 + ((lane & 16) ? 8 : 0) + rl;
                int kunit = 2 * ks8 + ((lane & 8) ? 1 : 0);
                uint32_t kaddr = ks_u32 + (uint32_t)(krow * 128)
                               + (uint32_t)(((kunit ^ (krow & 7)) * 16));
                uint32_t b0, b1, b2, b3;
                ldsm4(b0, b1, b2, b3, kaddr);
                mma_f16(s[2 * p][0], s[2 * p][1], s[2 * p][2], s[2 * p][3],
                        qa[ks8][0], qa[ks8][1], qa[ks8][2], qa[ks8][3], b0, b1);
                mma_f16(s[2 * p + 1][0], s[2 * p + 1][1], s[2 * p + 1][2], s[2 * p + 1][3],
                        qa[ks8][0], qa[ks8][1], qa[ks8][2], qa[ks8][3], b2, b3);
            }
        }

        // ---- causal mask ----
        const int row0 = m0 + wrow + g;
        const int row1 = row0 + 8;
        if (n0 + AN - 1 > m0 + wrow) {
#pragma unroll
            for (int nj = 0; nj < 8; nj++) {
                int col = n0 + nj * 8 + 2 * t;
                if (col     > row0) s[nj][0] = -1e30f;
                if (col + 1 > row0) s[nj][1] = -1e30f;
                if (col     > row1) s[nj][2] = -1e30f;
                if (col + 1 > row1) s[nj][3] = -1e30f;
            }
        }

        // ---- online softmax (base-2, packed-half exp) ----
        float rm0 = -1e30f, rm1 = -1e30f;
#pragma unroll
        for (int nj = 0; nj < 8; nj++) {
            rm0 = fmaxf(rm0, fmaxf(s[nj][0], s[nj][1]));
            rm1 = fmaxf(rm1, fmaxf(s[nj][2], s[nj][3]));
        }
        rm0 = fmaxf(rm0, __shfl_xor_sync(0xffffffffu, rm0, 1));
        rm0 = fmaxf(rm0, __shfl_xor_sync(0xffffffffu, rm0, 2));
        rm1 = fmaxf(rm1, __shfl_xor_sync(0xffffffffu, rm1, 1));
        rm1 = fmaxf(rm1, __shfl_xor_sync(0xffffffffu, rm1, 2));
        float nm0 = fmaxf(mx0, rm0), nm1 = fmaxf(mx1, rm1);
        float al0 = exp2f(mx0 - nm0), al1 = exp2f(mx1 - nm1);
        mx0 = nm0; mx1 = nm1;

        float rs0 = 0.0f, rs1 = 0.0f;
#pragma unroll
        for (int nj = 0; nj < 8; nj++) {
            __half2 e01 = h2exp2(__floats2half2_rn(s[nj][0] - nm0, s[nj][1] - nm0));
            __half2 e23 = h2exp2(__floats2half2_rn(s[nj][2] - nm1, s[nj][3] - nm1));
            *(__half2*)(Pb + (wrow + g) * PBSTR + nj * 8 + 2 * t) = e01;
            *(__half2*)(Pb + (wrow + g + 8) * PBSTR + nj * 8 + 2 * t) = e23;
            float2 f01 = __half22float2(e01);
            float2 f23 = __half22float2(e23);
            rs0 += f01.x + f01.y;
            rs1 += f23.x + f23.y;
        }
        rs0 += __shfl_xor_sync(0xffffffffu, rs0, 1);
        rs0 += __shfl_xor_sync(0xffffffffu, rs0, 2);
        rs1 += __shfl_xor_sync(0xffffffffu, rs1, 1);
        rs1 += __shfl_xor_sync(0xffffffffu, rs1, 2);
        l0 = l0 * al0 + rs0;
        l1 = l1 * al1 + rs1;

        // skip O rescale when alpha == 1 warp-wide (exact no-op)
        bool need = (al0 != 1.0f) || (al1 != 1.0f);
        if (__any_sync(0xffffffffu, need)) {
#pragma unroll
            for (int nj = 0; nj < 8; nj++) {
                o[nj][0] *= al0; o[nj][1] *= al0;
                o[nj][2] *= al1; o[nj][3] *= al1;
            }
        }
        __syncwarp();   // P visible warp-wide (warp-private rows)

        // ---- O += P V ----
#pragma unroll
        for (int kp = 0; kp < 4; kp++) {
            uint32_t pa0, pa1, pa2, pa3;
            ldsm4(pa0, pa1, pa2, pa3,
                  pb_u32 + qrow_off + (uint32_t)(kp * 16 * 2));
#pragma unroll
            for (int p = 0; p < 4; p++) {
                int vrow = kp * 16 + ((lane & 8) ? 8 : 0) + rl;
                int vunit = 2 * p + ((lane & 16) ? 1 : 0);
                uint32_t vaddr = vs_u32 + (uint32_t)(vrow * 128)
                               + (uint32_t)(((vunit ^ (vrow & 7)) * 16));
                uint32_t b0, b1, b2, b3;
                ldsm4t(b0, b1, b2, b3, vaddr);
                mma_f16(o[2 * p][0], o[2 * p][1], o[2 * p][2], o[2 * p][3],
                        pa0, pa1, pa2, pa3, b0, b1);
                mma_f16(o[2 * p + 1][0], o[2 * p + 1][1], o[2 * p + 1][2], o[2 * p + 1][3],
                        pa0, pa1, pa2, pa3, b2, b3);
            }
        }
        __syncwarp();   // P reads done before next tile's P stores
    }

    // ---- normalize + write fp16 ----
    const float i0 = 1.0f / l0, i1 = 1.0f / l1;
    const int row0 = m0 + wrow + g;
    __half* ob0 = ao + ((size_t)(b * TSEQ + row0)) * CDIM + h * HD;
    __half* ob1 = ob0 + 8 * CDIM;
#pragma unroll
    for (int nj = 0; nj < 8; nj++) {
        *(__half2*)(ob0 + nj * 8 + 2 * t) =
            __floats2half2_rn(o[nj][0] * i0, o[nj][1] * i0);
        *(__half2*)(ob1 + nj * 8 + 2 * t) =
            __floats2half2_rn(o[nj][2] * i1, o[nj][3] * i1);
    }
}

// ---------------------------------------------------------------------------
// Host launcher
// ---------------------------------------------------------------------------
extern "C" void kernel_launch(void* const* d_in, const int* in_sizes, int n_in,
                              void* d_out, int out_size)
{
    const float* x       = (const float*)d_in[0];  // [2,2048,1024]
    const float* f_cos   = (const float*)d_in[1];  // [2048,32]
    const float* f_sin   = (const float*)d_in[2];  // [2048,32]
    const float* qkv_w   = (const float*)d_in[3];  // [3072,1024]
    const float* proj_w  = (const float*)d_in[4];  // [1024,1024]
    float* out = (float*)d_out;

    __half *qkv_ptr, *ao_ptr, *xr_ptr, *wq_ptr, *wp_ptr;
    cudaGetSymbolAddress((void**)&qkv_ptr, g_qkv);
    cudaGetSymbolAddress((void**)&ao_ptr,  g_ao);
    cudaGetSymbolAddress((void**)&xr_ptr,  g_xr);
    cudaGetSymbolAddress((void**)&wq_ptr,  g_wq);
    cudaGetSymbolAddress((void**)&wp_ptr,  g_wp);

    cudaFuncSetAttribute(gemm_f16_nt<0>,
                         cudaFuncAttributeMaxDynamicSharedMemorySize, GEMM_SMEM);
    cudaFuncSetAttribute(gemm_f16_nt<1>,
                         cudaFuncAttributeMaxDynamicSharedMemorySize, GEMM_SMEM);
    cudaFuncSetAttribute(attn_mma,
                         cudaFuncAttributeMaxDynamicSharedMemorySize, ATTN_SMEM);

    // 0) Convert x and both weights to fp16 (single launch)
    to_fp16_all<<<1024, 256>>>(
        (const float4*)x,      (__half2*)xr_ptr, BT * CDIM / 4,
        (const float4*)qkv_w,  (__half2*)wq_ptr, QKVDIM * CDIM / 4,
        (const float4*)proj_w, (__half2*)wp_ptr, CDIM * CDIM / 4);

    // 1) QKV projection with fused RoPE (+q scaling) epilogue, fp16 out
    {
        dim3 grid(QKVDIM / TN, BT / TM);
        gemm_f16_nt<1><<<grid, 256, GEMM_SMEM>>>(xr_ptr, wq_ptr, (void*)qkv_ptr,
                                                 BT, QKVDIM, CDIM,
                                                 f_cos, f_sin);
    }

    // 2) Causal flash attention
    {
        dim3 grid(TSEQ / AM, HEADS, BATCH);
        attn_mma<<<grid, 256, ATTN_SMEM>>>(qkv_ptr, ao_ptr);
    }

    // 3) Output projection (fp32 stores to d_out)
    {
        dim3 grid(CDIM / TN, BT / TM);
        gemm_f16_nt<0><<<grid, 256, GEMM_SMEM>>>(ao_ptr, wp_ptr, (void*)out,
                                                 BT, CDIM, CDIM,
                                                 nullptr, nullptr);
    }
}